// round 1
// baseline (speedup 1.0000x reference)
#include <cuda_runtime.h>
#include <cstdint>

#define NB   64
#define LL   16
#define IS   1024
#define TT   4064
#define MAXL 95
#define LNEPS 1e-12f

// ---------------- scratch (static device globals; no runtime alloc) ----------
__device__ float g_u[NB * IS];            // U(ctx)            [64,1024]
__device__ float g_uv[NB * IS];           // V_w^T @ u         [64,1024]
__device__ float g_c[NB];                 // u . V_b           [64]
__device__ float g_A[(size_t)TT * 2 * IS];// [pooled | ctx[seg]] [4064,2048]
__device__ float g_H[(size_t)TT * IS];    // encoder GEMM out  [4064,1024]
__device__ int   g_seg[TT];
__device__ int   g_pos[TT];

// ---------------- ragged row -> (segment, position) map ----------------------
__global__ void map_kernel(const int* __restrict__ l_hs) {
    __shared__ int offs[NB + 1];
    if (threadIdx.x == 0) {
        int s = 0;
        for (int b = 0; b < NB; b++) { offs[b] = s; s += l_hs[b]; }
        offs[NB] = s;
    }
    __syncthreads();
    int b = threadIdx.x;
    int o = offs[b], n = offs[b + 1] - o;
    for (int i = 0; i < n; i++) { g_seg[o + i] = b; g_pos[o + i] = i; }
}

// ---------------- fill output with beta (padding rows LN -> beta) ------------
__global__ void fill_kernel(const float4* __restrict__ beta4, float4* __restrict__ out4) {
    int i = blockIdx.x * 256 + threadIdx.x;     // grid covers exactly 64*95*1024/4
    out4[i] = beta4[i & 255];
}

// ---------------- small GEMM: C[64,1024] = A[64,1024] @ W(^T) + bias ---------
// PHASE==1:  A = Ain(param=ctx), C[b,n] = sum_k A[b,k]*W[n,k] + bias[n] -> g_u
// PHASE==2:  A = g_u,            C[b,n] = sum_k A[b,k]*W[k,n]           -> g_uv
template<int PHASE>
__global__ void __launch_bounds__(256) gemm64_kernel(const float* __restrict__ Ain_param,
                                                     const float* __restrict__ W,
                                                     const float* __restrict__ bias) {
    __shared__ float As[64][17];   // [m][k], padded
    __shared__ float Ws[16][68];   // [k][n], padded (row stride 272B, 16B aligned)
    const float* Ain = (PHASE == 1) ? Ain_param : g_u;
    float*       Cout = (PHASE == 1) ? g_u : g_uv;
    const int n0 = blockIdx.x * 64;
    const int tid = threadIdx.x;
    const int tx = tid & 15, ty = tid >> 4;
    float acc[4][4] = {};
    for (int k0 = 0; k0 < IS; k0 += 16) {
        {   // A tile 64x16
            int m = tid >> 2, kk = (tid & 3) << 2;
            float4 v = *reinterpret_cast<const float4*>(&Ain[m * IS + k0 + kk]);
            As[m][kk] = v.x; As[m][kk + 1] = v.y; As[m][kk + 2] = v.z; As[m][kk + 3] = v.w;
        }
        if (PHASE == 1) {   // W accessed by rows n (transposed product)
            int n = tid >> 2, kk = (tid & 3) << 2;
            float4 v = *reinterpret_cast<const float4*>(&W[(size_t)(n0 + n) * IS + k0 + kk]);
            Ws[kk][n] = v.x; Ws[kk + 1][n] = v.y; Ws[kk + 2][n] = v.z; Ws[kk + 3][n] = v.w;
        } else {            // W accessed by rows k (plain product)
            int k = tid >> 4, n4 = (tid & 15) << 2;
            float4 v = *reinterpret_cast<const float4*>(&W[(size_t)(k0 + k) * IS + n0 + n4]);
            *reinterpret_cast<float4*>(&Ws[k][n4]) = v;
        }
        __syncthreads();
#pragma unroll
        for (int kk = 0; kk < 16; kk++) {
            float a[4];
#pragma unroll
            for (int i = 0; i < 4; i++) a[i] = As[ty * 4 + i][kk];
            float4 bv = *reinterpret_cast<const float4*>(&Ws[kk][tx * 4]);
            float b[4] = {bv.x, bv.y, bv.z, bv.w};
#pragma unroll
            for (int i = 0; i < 4; i++)
#pragma unroll
                for (int j = 0; j < 4; j++) acc[i][j] += a[i] * b[j];
        }
        __syncthreads();
    }
#pragma unroll
    for (int i = 0; i < 4; i++) {
        int m = ty * 4 + i;
#pragma unroll
        for (int j = 0; j < 4; j++) {
            int n = n0 + tx * 4 + j;
            float v = acc[i][j];
            if (PHASE == 1) v += bias[n];
            Cout[m * IS + n] = v;
        }
    }
}

// ---------------- c[b] = u[b] . V_b ------------------------------------------
__global__ void cdot_kernel(const float* __restrict__ Vb) {
    int wid = threadIdx.x >> 5, lane = threadIdx.x & 31;
    int b = blockIdx.x * 8 + wid;
    float s = 0.f;
    for (int k = lane; k < IS; k += 32) s += g_u[b * IS + k] * Vb[k];
#pragma unroll
    for (int o = 16; o; o >>= 1) s += __shfl_xor_sync(0xffffffffu, s, o);
    if (lane == 0) g_c[b] = s;
}

// ---------------- attention: scores -> softmax -> pooled; build g_A ----------
__global__ void __launch_bounds__(256) attn_kernel(const float* __restrict__ wemb,
                                                   const float* __restrict__ ctx) {
    extern __shared__ float sw[];     // [16][1024] = 64KB
    __shared__ float ssc[32];
    const int t = blockIdx.x;
    const int tid = threadIdx.x;
    const int seg = g_seg[t];
    // load wemb[t] into smem (one pass over the 266MB tensor total)
    {
        const float4* wt4 = reinterpret_cast<const float4*>(wemb + (size_t)t * LL * IS);
        float4* sw4 = reinterpret_cast<float4*>(sw);
        for (int i = tid; i < LL * IS / 4; i += 256) sw4[i] = wt4[i];
    }
    __syncthreads();
    const float* uvp = g_uv + seg * IS;
    const int wid = tid >> 5, lane = tid & 31;
    for (int l = wid; l < LL; l += 8) {
        float s = 0.f;
        const float* row = sw + l * IS;
        for (int k = lane; k < IS; k += 32) s += row[k] * uvp[k];
#pragma unroll
        for (int o = 16; o; o >>= 1) s += __shfl_xor_sync(0xffffffffu, s, o);
        if (lane == 0) ssc[l] = s + g_c[seg];
    }
    __syncthreads();
    if (tid < 32) {   // softmax over 16 in one warp
        float v = (lane < LL) ? ssc[lane] : -3.0e38f;
        float m = v;
#pragma unroll
        for (int o = 16; o; o >>= 1) m = fmaxf(m, __shfl_xor_sync(0xffffffffu, m, o));
        float e = (lane < LL) ? __expf(v - m) : 0.f;
        float s = e;
#pragma unroll
        for (int o = 16; o; o >>= 1) s += __shfl_xor_sync(0xffffffffu, s, o);
        if (lane < LL) ssc[lane] = e / s;
    }
    __syncthreads();
    float at[LL];
#pragma unroll
    for (int l = 0; l < LL; l++) at[l] = ssc[l];
    float* Ar = g_A + (size_t)t * (2 * IS);
    for (int d = tid; d < IS; d += 256) {
        float acc = 0.f;
#pragma unroll
        for (int l = 0; l < LL; l++) acc += at[l] * sw[l * IS + d];
        Ar[d] = acc;                      // pooled
    }
    const float* cr = ctx + seg * IS;
    for (int d = tid; d < IS; d += 256) Ar[IS + d] = cr[d];   // ctx[seg]
}

// ---------------- encoder GEMM: H[T,1024] = g_A[T,2048] @ enc_w^T + enc_b ----
__global__ void __launch_bounds__(256) gemm_enc_kernel(const float* __restrict__ Bw,
                                                       const float* __restrict__ bias) {
    __shared__ float As[16][128];
    __shared__ float Bs[16][128];
    const int m0 = blockIdx.y * 128;
    const int n0 = blockIdx.x * 128;
    const int tid = threadIdx.x;
    const int tx = tid & 15, ty = tid >> 4;
    float acc[8][8] = {};
    for (int k0 = 0; k0 < 2 * IS; k0 += 16) {
#pragma unroll
        for (int j = 0; j < 2; j++) {
            int f4 = tid * 2 + j;
            int r = f4 >> 2, kk = (f4 & 3) << 2;
            float4 av = make_float4(0.f, 0.f, 0.f, 0.f);
            int gm = m0 + r;
            if (gm < TT)
                av = *reinterpret_cast<const float4*>(&g_A[(size_t)gm * (2 * IS) + k0 + kk]);
            As[kk][r] = av.x; As[kk + 1][r] = av.y; As[kk + 2][r] = av.z; As[kk + 3][r] = av.w;
            float4 bv = *reinterpret_cast<const float4*>(&Bw[(size_t)(n0 + r) * (2 * IS) + k0 + kk]);
            Bs[kk][r] = bv.x; Bs[kk + 1][r] = bv.y; Bs[kk + 2][r] = bv.z; Bs[kk + 3][r] = bv.w;
        }
        __syncthreads();
#pragma unroll
        for (int kk = 0; kk < 16; kk++) {
            float a[8], b[8];
            *reinterpret_cast<float4*>(&a[0]) = *reinterpret_cast<const float4*>(&As[kk][ty * 8]);
            *reinterpret_cast<float4*>(&a[4]) = *reinterpret_cast<const float4*>(&As[kk][ty * 8 + 4]);
            *reinterpret_cast<float4*>(&b[0]) = *reinterpret_cast<const float4*>(&Bs[kk][tx * 8]);
            *reinterpret_cast<float4*>(&b[4]) = *reinterpret_cast<const float4*>(&Bs[kk][tx * 8 + 4]);
#pragma unroll
            for (int i = 0; i < 8; i++)
#pragma unroll
                for (int j = 0; j < 8; j++) acc[i][j] += a[i] * b[j];
        }
        __syncthreads();
    }
#pragma unroll
    for (int i = 0; i < 8; i++) {
        int gm = m0 + ty * 8 + i;
        if (gm < TT) {
#pragma unroll
            for (int j = 0; j < 8; j++) {
                int n = n0 + tx * 8 + j;
                g_H[(size_t)gm * IS + n] = acc[i][j] + bias[n];
            }
        }
    }
}

// ---------------- LayerNorm + ragged scatter ---------------------------------
__global__ void __launch_bounds__(256) ln_kernel(const float* __restrict__ gamma,
                                                 const float* __restrict__ beta,
                                                 float* __restrict__ out) {
    __shared__ float rs[8], rs2[8];
    const int t = blockIdx.x;
    const int tid = threadIdx.x;
    const float* h = g_H + (size_t)t * IS;
    float s = 0.f, s2 = 0.f;
    for (int d = tid; d < IS; d += 256) { float v = h[d]; s += v; s2 += v * v; }
    const int wid = tid >> 5, lane = tid & 31;
#pragma unroll
    for (int o = 16; o; o >>= 1) {
        s  += __shfl_xor_sync(0xffffffffu, s, o);
        s2 += __shfl_xor_sync(0xffffffffu, s2, o);
    }
    if (lane == 0) { rs[wid] = s; rs2[wid] = s2; }
    __syncthreads();
    if (tid == 0) {
        float S = 0.f, S2 = 0.f;
        for (int w = 0; w < 8; w++) { S += rs[w]; S2 += rs2[w]; }
        rs[0] = S; rs2[0] = S2;
    }
    __syncthreads();
    const float mean = rs[0] * (1.0f / IS);
    const float var  = rs2[0] * (1.0f / IS) - mean * mean;
    const float inv  = rsqrtf(var + LNEPS);
    float* orow = out + ((size_t)(g_seg[t] * MAXL + g_pos[t])) * IS;
    for (int d = tid; d < IS; d += 256)
        orow[d] = gamma[d] * (h[d] - mean) * inv + beta[d];
}

// ---------------- launch ------------------------------------------------------
extern "C" void kernel_launch(void* const* d_in, const int* in_sizes, int n_in,
                              void* d_out, int out_size) {
    const float* ctx   = (const float*)d_in[0];
    const float* wemb  = (const float*)d_in[1];
    const int*   l_hs  = (const int*)  d_in[3];
    // last 8 inputs are always U_w, U_b, V_w, V_b, enc_w, enc_b, gamma, beta
    const float* U_w   = (const float*)d_in[n_in - 8];
    const float* U_b   = (const float*)d_in[n_in - 7];
    const float* V_w   = (const float*)d_in[n_in - 6];
    const float* V_b   = (const float*)d_in[n_in - 5];
    const float* enc_w = (const float*)d_in[n_in - 4];
    const float* enc_b = (const float*)d_in[n_in - 3];
    const float* gamma = (const float*)d_in[n_in - 2];
    const float* beta  = (const float*)d_in[n_in - 1];
    float* out = (float*)d_out;

    cudaFuncSetAttribute(attn_kernel, cudaFuncAttributeMaxDynamicSharedMemorySize, LL * IS * 4);

    map_kernel<<<1, NB>>>(l_hs);
    fill_kernel<<<(NB * MAXL * IS / 4) / 256, 256>>>((const float4*)beta, (float4*)out);
    gemm64_kernel<1><<<IS / 64, 256>>>(ctx, U_w, U_b);
    cdot_kernel<<<NB / 8, 256>>>(V_b);
    gemm64_kernel<2><<<IS / 64, 256>>>(ctx, V_w, nullptr);
    attn_kernel<<<TT, 256, LL * IS * 4>>>(wemb, ctx);
    gemm_enc_kernel<<<dim3(IS / 128, (TT + 127) / 128), 256>>>(enc_w, enc_b);
    ln_kernel<<<TT, 256>>>(gamma, beta, out);
}